// round 5
// baseline (speedup 1.0000x reference)
#include <cuda_runtime.h>

#define Gn 1024
#define Tn 200
#define Sn 16
#define Mn 4
#define SW 20   // padded row stride (floats) for 16-row matrices

// One CTA (64 threads, 2 warps) per group. Lane owns cov row i=tid>>2,
// cols jb=(tid&3)*4 .. +3 (4 registers). Cross-warp sync = cheap 2-warp BAR.
__global__ __launch_bounds__(64)
void kalman_kernel(const float* __restrict__ y,        // [G,T,M]
                   const float* __restrict__ F,        // [G,T,S,S]
                   const float* __restrict__ H,        // [G,T,M,S]
                   const float* __restrict__ Q,        // [G,T,S,S]
                   const float* __restrict__ R,        // [G,T,M,M]
                   const float* __restrict__ init_mean,// [G,S]
                   const float* __restrict__ init_cov, // [G,S,S]
                   float* __restrict__ out_means,      // [G,T,S]
                   float* __restrict__ out_covs,       // [G,T,S,S]
                   float* __restrict__ out_R,          // [G,T,M,M]
                   float* __restrict__ out_H)          // [G,T,M,S]
{
    __shared__ float sm[1256];
    float* sF     = sm;            // [16][SW]
    float* sP     = sm + 320;      // [16][SW]  cov_u
    float* sT1    = sm + 640;      // [16][SW]  F @ cov_u
    float* sHP    = sm + 960;      // [4][SW]
    float* sH     = sm + 1040;     // [4][SW]
    float* sK     = sm + 1120;     // [16][4]
    float* sSinv  = sm + 1184;     // [4][4]
    float* sMean  = sm + 1200;     // [16]  (carry)
    float* sMeanU = sm + 1216;     // [16]
    float* sResid = sm + 1232;     // [4]
    float* sSsig  = sm + 1236;     // [16]

    const int tid = threadIdx.x;
    const int i   = tid >> 2;          // cov row 0..15
    const int c   = tid & 3;
    const int jb  = c * 4;             // col block 0,4,8,12
    const int g   = blockIdx.x;

    const float* yG = y + (size_t)g * Tn * Mn;
    const float* FG = F + (size_t)g * Tn * Sn * Sn;
    const float* HG = H + (size_t)g * Tn * Mn * Sn;
    const float* QG = Q + (size_t)g * Tn * Sn * Sn;
    const float* RG = R + (size_t)g * Tn * Mn * Mn;
    float* mOut = out_means + (size_t)g * Tn * Sn;
    float* cOut = out_covs  + (size_t)g * Tn * Sn * Sn;
    float* rOut = out_R     + (size_t)g * Tn * Mn * Mn;
    float* hOut = out_H     + (size_t)g * Tn * Mn * Sn;

    // ---- carry: cov row-block in regs, mean in smem ----
    float cCov[4];
    {
        float4 a = *(const float4*)(init_cov + (size_t)g * 256 + tid * 4);
        cCov[0] = a.x; cCov[1] = a.y; cCov[2] = a.z; cCov[3] = a.w;
    }
    if (tid < Sn) sMean[tid] = init_mean[(size_t)g * Sn + tid];

    // ---- prefetch t=0 ----
    float4 pF = *(const float4*)(FG + tid * 4);
    float4 pQ = *(const float4*)(QG + tid * 4);
    float pH = HG[tid];
    float pR = (tid < 16) ? RG[tid] : 0.0f;
    float pY = (tid < 4)  ? yG[tid] : 0.0f;

    __syncthreads();

    for (int t = 0; t < Tn; ++t) {
        // capture current-step small inputs before prefetch clobbers them
        const float qC0 = pQ.x, qC1 = pQ.y, qC2 = pQ.z, qC3 = pQ.w;
        const float rR = pR, cy = pY, hC = pH;

        // ---- emit outputs for time t ----
        *(float4*)(cOut + (size_t)t * 256 + tid * 4) =
            make_float4(cCov[0], cCov[1], cCov[2], cCov[3]);
        if (tid < Sn) mOut[t * Sn + tid] = sMean[tid];
        hOut[t * 64 + tid] = hC;                 // H passthrough
        if (tid < 16) rOut[t * 16 + tid] = rR;   // R passthrough

        // ---- stage F, H ----
        *(float4*)(sF + i * SW + jb) = pF;
        sH[(tid >> 4) * SW + (tid & 15)] = hC;
        __syncthreads();   // S1

        // ---- F row i -> regs ----
        float fr[16];
        {
            const float4 a = *(const float4*)(sF + i * SW);
            const float4 b = *(const float4*)(sF + i * SW + 4);
            const float4 d = *(const float4*)(sF + i * SW + 8);
            const float4 e = *(const float4*)(sF + i * SW + 12);
            fr[0]=a.x; fr[1]=a.y; fr[2]=a.z; fr[3]=a.w;
            fr[4]=b.x; fr[5]=b.y; fr[6]=b.z; fr[7]=b.w;
            fr[8]=d.x; fr[9]=d.y; fr[10]=d.z; fr[11]=d.w;
            fr[12]=e.x; fr[13]=e.y; fr[14]=e.z; fr[15]=e.w;
        }

        // ---- prefetch t+1 (overlaps compute) ----
        if (t + 1 < Tn) {
            pF = *(const float4*)(FG + (size_t)(t + 1) * 256 + tid * 4);
            pQ = *(const float4*)(QG + (size_t)(t + 1) * 256 + tid * 4);
            pH = HG[(size_t)(t + 1) * 64 + tid];
            if (tid < 16) pR = RG[(size_t)(t + 1) * 16 + tid];
            if (tid < 4)  pY = yG[(size_t)(t + 1) * 4 + tid];
        }

        // ---- Phase 1: HP[m][s] from register P (symmetry: P[n][s]=P[s][n]) ----
        {
            float hp[4];
            #pragma unroll
            for (int m = 0; m < 4; ++m) {
                const float4 h4 = *(const float4*)(sH + m * SW + jb);
                float p = h4.x * cCov[0] + h4.y * cCov[1] + h4.z * cCov[2] + h4.w * cCov[3];
                p += __shfl_xor_sync(0xffffffffu, p, 1);
                p += __shfl_xor_sync(0xffffffffu, p, 2);
                hp[m] = p;                    // HP[m][i], full, in all 4 lanes of row i
            }
            sHP[c * SW + i] = hp[c];          // lane writes m=c
        }
        // resid[m] = y[m] - H[m] . mean   (16 lanes)
        if (tid < 16) {
            const int m = tid >> 2, cc = tid & 3;
            const float4 h4 = *(const float4*)(sH + m * SW + cc * 4);
            const float4 mu = *(const float4*)(sMean + cc * 4);
            float p = h4.x * mu.x + h4.y * mu.y + h4.z * mu.z + h4.w * mu.w;
            p += __shfl_xor_sync(0xffffu, p, 1);
            p += __shfl_xor_sync(0xffffu, p, 2);
            const float ym = __shfl_sync(0xffffu, cy, m);
            if (cc == 0) sResid[m] = ym - p;
        }
        __syncthreads();   // S2

        // ---- Phase 2+3 (warp 0): Ssig, then 4x4 inverse ----
        if (tid < 32) {
            if (tid < 16) {
                const int m = tid >> 2, k = tid & 3;
                float acc = rR;   // R[m][k] (lane tid = m*4+k holds it)
                #pragma unroll
                for (int cc = 0; cc < 4; ++cc) {
                    const float4 a = *(const float4*)(sHP + m * SW + cc * 4);
                    const float4 b = *(const float4*)(sH  + k * SW + cc * 4);
                    acc += a.x * b.x + a.y * b.y + a.z * b.z + a.w * b.w;
                }
                sSsig[tid] = acc;
            }
            __syncwarp();
            if (tid < 16) {
                const int ii = tid >> 2, jj = tid & 3;
                const int r0 = (ii == 0) ? 1 : 0;
                const int r1 = (ii <= 1) ? 2 : 1;
                const int r2 = (ii <= 2) ? 3 : 2;
                const int c0 = (jj == 0) ? 1 : 0;
                const int c1 = (jj <= 1) ? 2 : 1;
                const int c2 = (jj <= 2) ? 3 : 2;
                #define MM(a, b) sSsig[(a) * 4 + (b)]
                float d3 = MM(r0,c0) * (MM(r1,c1)*MM(r2,c2) - MM(r1,c2)*MM(r2,c1))
                         - MM(r0,c1) * (MM(r1,c0)*MM(r2,c2) - MM(r1,c2)*MM(r2,c0))
                         + MM(r0,c2) * (MM(r1,c0)*MM(r2,c1) - MM(r1,c1)*MM(r2,c0));
                #undef MM
                const float cof = ((ii + jj) & 1) ? -d3 : d3;
                float part = (ii == 0) ? sSsig[jj] * cof : 0.0f;
                part += __shfl_xor_sync(0xffffu, part, 1);
                part += __shfl_xor_sync(0xffffu, part, 2);
                const float det = __shfl_sync(0xffffu, part, 0);
                sSinv[jj * 4 + ii] = cof * (1.0f / det);
            }
        }
        __syncthreads();   // S3

        // ---- Phase 4: K[s][m] = Sinv[m][:] . HP[:][s]  (64 outputs) ----
        {
            const float4 sv = *(const float4*)(sSinv + c * 4);   // Sinv row m=c
            const float acc = sv.x * sHP[0 * SW + i] + sv.y * sHP[1 * SW + i]
                            + sv.z * sHP[2 * SW + i] + sv.w * sHP[3 * SW + i];
            sK[i * 4 + c] = acc;
        }
        __syncthreads();   // S4

        // ---- Phase 5: cov_u = P - K @ HP (regs, own block); mean_u ----
        {
            const float4 kk = *(const float4*)(sK + i * 4);
            const float4 h0 = *(const float4*)(sHP + 0 * SW + jb);
            const float4 h1 = *(const float4*)(sHP + 1 * SW + jb);
            const float4 h2 = *(const float4*)(sHP + 2 * SW + jb);
            const float4 h3 = *(const float4*)(sHP + 3 * SW + jb);
            float cu0 = cCov[0] - kk.x*h0.x - kk.y*h1.x - kk.z*h2.x - kk.w*h3.x;
            float cu1 = cCov[1] - kk.x*h0.y - kk.y*h1.y - kk.z*h2.y - kk.w*h3.y;
            float cu2 = cCov[2] - kk.x*h0.z - kk.y*h1.z - kk.z*h2.z - kk.w*h3.z;
            float cu3 = cCov[3] - kk.x*h0.w - kk.y*h1.w - kk.z*h2.w - kk.w*h3.w;
            *(float4*)(sP + i * SW + jb) = make_float4(cu0, cu1, cu2, cu3);
        }
        if (tid < 16) {
            const float4 kk = *(const float4*)(sK + tid * 4);
            const float4 rs = *(const float4*)(sResid);
            sMeanU[tid] = sMean[tid] + kk.x*rs.x + kk.y*rs.y + kk.z*rs.z + kk.w*rs.w;
        }
        __syncthreads();   // S5

        // ---- Phase 6: T1 = F @ cov_u (own block); mean_p ----
        {
            float t0 = 0.f, t1_ = 0.f, t2 = 0.f, t3 = 0.f;
            #pragma unroll
            for (int k = 0; k < 16; ++k) {
                const float4 p = *(const float4*)(sP + k * SW + jb);
                const float fk = fr[k];
                t0 += fk * p.x; t1_ += fk * p.y; t2 += fk * p.z; t3 += fk * p.w;
            }
            *(float4*)(sT1 + i * SW + jb) = make_float4(t0, t1_, t2, t3);
        }
        {
            const float4 mu = *(const float4*)(sMeanU + jb);
            float pm = fr[jb] * mu.x + fr[jb + 1] * mu.y
                     + fr[jb + 2] * mu.z + fr[jb + 3] * mu.w;
            pm += __shfl_xor_sync(0xffffffffu, pm, 1);
            pm += __shfl_xor_sync(0xffffffffu, pm, 2);
            if (c == 0) sMean[i] = pm;
        }
        __syncthreads();   // S6

        // ---- Phase 7: cov[i][jb+r] = Q + T1[jb+r][:] . F[i][:] (cov symmetry) ----
        {
            float a0 = qC0, a1 = qC1, a2 = qC2, a3 = qC3;
            #pragma unroll
            for (int kc = 0; kc < 4; ++kc) {
                const float4 t0 = *(const float4*)(sT1 + (jb + 0) * SW + kc * 4);
                const float4 t1_ = *(const float4*)(sT1 + (jb + 1) * SW + kc * 4);
                const float4 t2 = *(const float4*)(sT1 + (jb + 2) * SW + kc * 4);
                const float4 t3 = *(const float4*)(sT1 + (jb + 3) * SW + kc * 4);
                const float f0 = fr[kc * 4], f1 = fr[kc * 4 + 1];
                const float f2 = fr[kc * 4 + 2], f3 = fr[kc * 4 + 3];
                a0 += f0 * t0.x + f1 * t0.y + f2 * t0.z + f3 * t0.w;
                a1 += f0 * t1_.x + f1 * t1_.y + f2 * t1_.z + f3 * t1_.w;
                a2 += f0 * t2.x + f1 * t2.y + f2 * t2.z + f3 * t2.w;
                a3 += f0 * t3.x + f1 * t3.y + f2 * t3.z + f3 * t3.w;
            }
            cCov[0] = a0; cCov[1] = a1; cCov[2] = a2; cCov[3] = a3;
        }
        // next-iter staging only touches sF/sH (last read before S3) — safe
    }
}

extern "C" void kernel_launch(void* const* d_in, const int* in_sizes, int n_in,
                              void* d_out, int out_size) {
    const float* y  = (const float*)d_in[0];
    const float* F  = (const float*)d_in[1];
    const float* H  = (const float*)d_in[2];
    const float* Q  = (const float*)d_in[3];
    const float* R  = (const float*)d_in[4];
    const float* im = (const float*)d_in[5];
    const float* ic = (const float*)d_in[6];

    float* out       = (float*)d_out;
    float* out_means = out;                                    // G*T*S
    float* out_covs  = out_means + (size_t)Gn * Tn * Sn;       // G*T*S*S
    float* out_R     = out_covs  + (size_t)Gn * Tn * Sn * Sn;  // G*T*M*M
    float* out_H     = out_R     + (size_t)Gn * Tn * Mn * Mn;  // G*T*M*S

    kalman_kernel<<<Gn, 64>>>(y, F, H, Q, R, im, ic,
                              out_means, out_covs, out_R, out_H);
}

// round 9
// speedup vs baseline: 2.1229x; 2.1229x over previous
#include <cuda_runtime.h>

#define Gn 1024
#define Tn 200
#define Sn 16
#define Mn 4
#define SW 20   // padded row stride for [16]-row / [4]-row smem matrices

// One 32-thread CTA per group. Lane l: row i=l>>1, half=l&1, cols jb=half*8..+7.
// Carry: cov row-block in registers, mean in smem. __syncwarp only.
__global__ __launch_bounds__(32)
void kalman_kernel(const float* __restrict__ y,        // [G,T,M]
                   const float* __restrict__ F,        // [G,T,S,S]
                   const float* __restrict__ H,        // [G,T,M,S]
                   const float* __restrict__ Q,        // [G,T,S,S]
                   const float* __restrict__ R,        // [G,T,M,M]
                   const float* __restrict__ init_mean,// [G,S]
                   const float* __restrict__ init_cov, // [G,S,S]
                   float* __restrict__ out_means,      // [G,T,S]
                   float* __restrict__ out_covs,       // [G,T,S,S]
                   float* __restrict__ out_R,          // [G,T,M,M]
                   float* __restrict__ out_H)          // [G,T,M,S]
{
    __shared__ float sm[928];
    float* sH     = sm;          // [4][16] contiguous
    float* sHP    = sm + 64;     // [4][SW]
    float* sP     = sm + 144;    // [16][SW]  cov_u
    float* sT1    = sm + 464;    // [16][SW]  F @ cov_u
    float* sK     = sm + 784;    // [16][4]
    float* sSinv  = sm + 848;    // [4][4]
    float* sSsig  = sm + 864;    // [16]
    float* sMean  = sm + 880;    // [16] carry
    float* sMeanU = sm + 896;    // [16]
    float* sResid = sm + 912;    // [4]

    const int lane = threadIdx.x;
    const int i    = lane >> 1;
    const int half = lane & 1;
    const int jb   = half * 8;
    const int g    = blockIdx.x;

    const float* yG = y + (size_t)g * Tn * Mn;
    const float* FG = F + (size_t)g * Tn * Sn * Sn;
    const float* HG = H + (size_t)g * Tn * Mn * Sn;
    const float* QG = Q + (size_t)g * Tn * Sn * Sn;
    const float* RG = R + (size_t)g * Tn * Mn * Mn;
    float* mOut = out_means + (size_t)g * Tn * Sn;
    float* cOut = out_covs  + (size_t)g * Tn * Sn * Sn;
    float* rOut = out_R     + (size_t)g * Tn * Mn * Mn;
    float* hOut = out_H     + (size_t)g * Tn * Mn * Sn;

    // ---- carry ----
    float cCov[8];
    {
        const float4 a = *(const float4*)(init_cov + (size_t)g * 256 + i * 16 + jb);
        const float4 b = *(const float4*)(init_cov + (size_t)g * 256 + i * 16 + jb + 4);
        cCov[0]=a.x; cCov[1]=a.y; cCov[2]=a.z; cCov[3]=a.w;
        cCov[4]=b.x; cCov[5]=b.y; cCov[6]=b.z; cCov[7]=b.w;
    }
    if (lane < Sn) sMean[lane] = init_mean[(size_t)g * Sn + lane];

    // ---- prefetch t=0 ----
    float pF[8], pQ[8];
    {
        const float4 a = *(const float4*)(FG + lane * 8);
        const float4 b = *(const float4*)(FG + lane * 8 + 4);
        pF[0]=a.x; pF[1]=a.y; pF[2]=a.z; pF[3]=a.w; pF[4]=b.x; pF[5]=b.y; pF[6]=b.z; pF[7]=b.w;
        const float4 c = *(const float4*)(QG + lane * 8);
        const float4 d = *(const float4*)(QG + lane * 8 + 4);
        pQ[0]=c.x; pQ[1]=c.y; pQ[2]=c.z; pQ[3]=c.w; pQ[4]=d.x; pQ[5]=d.y; pQ[6]=d.z; pQ[7]=d.w;
    }
    float2 pH = *(const float2*)(HG + lane * 2);
    float pR = (lane < 16) ? RG[lane] : 0.0f;
    float pY = (lane < 4)  ? yG[lane] : 0.0f;

    __syncwarp();

    for (int t = 0; t < Tn; ++t) {
        const float rR = pR;   // R element for this t (phase 2 runs after prefetch)
        const float cy = pY;

        // ---- emit outputs for time t ----
        *(float4*)(cOut + (size_t)t * 256 + i * 16 + jb) =
            make_float4(cCov[0], cCov[1], cCov[2], cCov[3]);
        *(float4*)(cOut + (size_t)t * 256 + i * 16 + jb + 4) =
            make_float4(cCov[4], cCov[5], cCov[6], cCov[7]);
        if (lane < Sn) mOut[t * Sn + lane] = sMean[lane];
        *(float2*)(hOut + t * 64 + lane * 2) = pH;        // H passthrough
        if (lane < 16) rOut[t * 16 + lane] = rR;          // R passthrough

        // ---- stage H ----
        *(float2*)(sH + lane * 2) = pH;

        // ---- F row i -> regs via pair shfl (no smem) ----
        float fr[16];
        #pragma unroll
        for (int r = 0; r < 8; ++r) {
            const float o = __shfl_xor_sync(0xffffffffu, pF[r], 1);
            fr[r]     = half ? o     : pF[r];
            fr[8 + r] = half ? pF[r] : o;
        }
        __syncwarp();   // S1: sH visible

        // ---- prefetch t+1 F/H/R/y (Q prefetched at loop end) ----
        if (t + 1 < Tn) {
            const float4 a = *(const float4*)(FG + (size_t)(t + 1) * 256 + lane * 8);
            const float4 b = *(const float4*)(FG + (size_t)(t + 1) * 256 + lane * 8 + 4);
            pF[0]=a.x; pF[1]=a.y; pF[2]=a.z; pF[3]=a.w; pF[4]=b.x; pF[5]=b.y; pF[6]=b.z; pF[7]=b.w;
            pH = *(const float2*)(HG + (size_t)(t + 1) * 64 + lane * 2);
            if (lane < 16) pR = RG[(size_t)(t + 1) * 16 + lane];
            if (lane < 4)  pY = yG[(size_t)(t + 1) * 4 + lane];
        }

        // ---- Phase 1: HP[m][i] from register P rows (P symmetric) ----
        {
            float hp[4];
            #pragma unroll
            for (int m = 0; m < 4; ++m) {
                const float4 a = *(const float4*)(sH + m * 16 + jb);
                const float4 b = *(const float4*)(sH + m * 16 + jb + 4);
                float p = a.x*cCov[0] + a.y*cCov[1] + a.z*cCov[2] + a.w*cCov[3]
                        + b.x*cCov[4] + b.y*cCov[5] + b.z*cCov[6] + b.w*cCov[7];
                p += __shfl_xor_sync(0xffffffffu, p, 1);
                hp[m] = p;
            }
            const float sa = half ? hp[2] : hp[0];
            const float sb = half ? hp[3] : hp[1];
            sHP[(half * 2) * SW + i]     = sa;
            sHP[(half * 2 + 1) * SW + i] = sb;
        }
        // resid[m] = y[m] - H[m].mean  (lanes 0..15)
        if (lane < 16) {
            const int m = lane >> 2, cc = lane & 3;
            const float4 h4 = *(const float4*)(sH + m * 16 + cc * 4);
            const float4 mu = *(const float4*)(sMean + cc * 4);
            float p = h4.x*mu.x + h4.y*mu.y + h4.z*mu.z + h4.w*mu.w;
            p += __shfl_xor_sync(0xffffu, p, 1);
            p += __shfl_xor_sync(0xffffu, p, 2);
            const float ym = __shfl_sync(0xffffu, cy, m);
            if (cc == 0) sResid[m] = ym - p;
        }
        __syncwarp();   // S2: sHP, sResid

        // ---- Phase 2: Ssig = HP @ H' + R  (lanes 0..15) ----
        if (lane < 16) {
            const int m = lane >> 2, k = lane & 3;
            float acc = rR;
            #pragma unroll
            for (int cc = 0; cc < 4; ++cc) {
                const float4 a = *(const float4*)(sHP + m * SW + cc * 4);
                const float4 b = *(const float4*)(sH + k * 16 + cc * 4);
                acc += a.x*b.x + a.y*b.y + a.z*b.z + a.w*b.w;
            }
            sSsig[lane] = acc;
        }
        __syncwarp();   // S3: sSsig

        // ---- Phase 3: 4x4 inverse via cofactors (lanes 0..15) ----
        if (lane < 16) {
            const int ii = lane >> 2, jj = lane & 3;
            const int r0 = (ii == 0) ? 1 : 0;
            const int r1 = (ii <= 1) ? 2 : 1;
            const int r2 = (ii <= 2) ? 3 : 2;
            const int c0 = (jj == 0) ? 1 : 0;
            const int c1 = (jj <= 1) ? 2 : 1;
            const int c2 = (jj <= 2) ? 3 : 2;
            #define MM(a, b) sSsig[(a) * 4 + (b)]
            float d3 = MM(r0,c0) * (MM(r1,c1)*MM(r2,c2) - MM(r1,c2)*MM(r2,c1))
                     - MM(r0,c1) * (MM(r1,c0)*MM(r2,c2) - MM(r1,c2)*MM(r2,c0))
                     + MM(r0,c2) * (MM(r1,c0)*MM(r2,c1) - MM(r1,c1)*MM(r2,c0));
            #undef MM
            const float cof = ((ii + jj) & 1) ? -d3 : d3;
            float part = (ii == 0) ? sSsig[jj] * cof : 0.0f;
            part += __shfl_xor_sync(0xffffu, part, 1);
            part += __shfl_xor_sync(0xffffu, part, 2);
            const float det = __shfl_sync(0xffffu, part, 0);
            sSinv[jj * 4 + ii] = cof * (1.0f / det);
        }
        __syncwarp();   // S4: sSinv

        // ---- Phase 4: K[i][mb], K[i][mb+1] (2 per lane) ----
        {
            const int mb = half * 2;
            const float4 s0 = *(const float4*)(sSinv + mb * 4);
            const float4 s1 = *(const float4*)(sSinv + mb * 4 + 4);
            const float h0 = sHP[0 * SW + i], h1 = sHP[1 * SW + i];
            const float h2 = sHP[2 * SW + i], h3 = sHP[3 * SW + i];
            const float k0 = s0.x*h0 + s0.y*h1 + s0.z*h2 + s0.w*h3;
            const float k1 = s1.x*h0 + s1.y*h1 + s1.z*h2 + s1.w*h3;
            *(float2*)(sK + i * 4 + mb) = make_float2(k0, k1);
        }
        __syncwarp();   // S5: sK

        // ---- Phase 5: cov_u = P - K@HP (own block -> sP); mean_u ----
        {
            const float4 kk = *(const float4*)(sK + i * 4);
            const float4 a0 = *(const float4*)(sHP + 0 * SW + jb);
            const float4 b0 = *(const float4*)(sHP + 0 * SW + jb + 4);
            const float4 a1 = *(const float4*)(sHP + 1 * SW + jb);
            const float4 b1 = *(const float4*)(sHP + 1 * SW + jb + 4);
            const float4 a2 = *(const float4*)(sHP + 2 * SW + jb);
            const float4 b2 = *(const float4*)(sHP + 2 * SW + jb + 4);
            const float4 a3 = *(const float4*)(sHP + 3 * SW + jb);
            const float4 b3 = *(const float4*)(sHP + 3 * SW + jb + 4);
            const float c0 = cCov[0] - kk.x*a0.x - kk.y*a1.x - kk.z*a2.x - kk.w*a3.x;
            const float c1 = cCov[1] - kk.x*a0.y - kk.y*a1.y - kk.z*a2.y - kk.w*a3.y;
            const float c2 = cCov[2] - kk.x*a0.z - kk.y*a1.z - kk.z*a2.z - kk.w*a3.z;
            const float c3 = cCov[3] - kk.x*a0.w - kk.y*a1.w - kk.z*a2.w - kk.w*a3.w;
            const float c4 = cCov[4] - kk.x*b0.x - kk.y*b1.x - kk.z*b2.x - kk.w*b3.x;
            const float c5 = cCov[5] - kk.x*b0.y - kk.y*b1.y - kk.z*b2.y - kk.w*b3.y;
            const float c6 = cCov[6] - kk.x*b0.z - kk.y*b1.z - kk.z*b2.z - kk.w*b3.z;
            const float c7 = cCov[7] - kk.x*b0.w - kk.y*b1.w - kk.z*b2.w - kk.w*b3.w;
            *(float4*)(sP + i * SW + jb)     = make_float4(c0, c1, c2, c3);
            *(float4*)(sP + i * SW + jb + 4) = make_float4(c4, c5, c6, c7);
        }
        if (lane < 16) {
            const float4 kk = *(const float4*)(sK + lane * 4);
            const float4 rs = *(const float4*)(sResid);
            sMeanU[lane] = sMean[lane] + kk.x*rs.x + kk.y*rs.y + kk.z*rs.z + kk.w*rs.w;
        }
        __syncwarp();   // S6: sP, sMeanU

        // ---- Phase 6: T1 = F @ cov_u (own block -> sT1); mean_p ----
        {
            float t0=0.f, t1=0.f, t2=0.f, t3=0.f, t4=0.f, t5=0.f, t6=0.f, t7=0.f;
            #pragma unroll
            for (int k = 0; k < 16; ++k) {
                const float4 pa = *(const float4*)(sP + k * SW + jb);
                const float4 pb = *(const float4*)(sP + k * SW + jb + 4);
                const float fk = fr[k];
                t0 += fk*pa.x; t1 += fk*pa.y; t2 += fk*pa.z; t3 += fk*pa.w;
                t4 += fk*pb.x; t5 += fk*pb.y; t6 += fk*pb.z; t7 += fk*pb.w;
            }
            *(float4*)(sT1 + i * SW + jb)     = make_float4(t0, t1, t2, t3);
            *(float4*)(sT1 + i * SW + jb + 4) = make_float4(t4, t5, t6, t7);
        }
        {
            // mean_p[i] = F[i][:] . meanU  — partial over own half, pair-reduce
            const float4 ma = *(const float4*)(sMeanU + jb);
            const float4 mb4 = *(const float4*)(sMeanU + jb + 4);
            const float f0 = half ? fr[8]  : fr[0];
            const float f1 = half ? fr[9]  : fr[1];
            const float f2 = half ? fr[10] : fr[2];
            const float f3 = half ? fr[11] : fr[3];
            const float f4 = half ? fr[12] : fr[4];
            const float f5 = half ? fr[13] : fr[5];
            const float f6 = half ? fr[14] : fr[6];
            const float f7 = half ? fr[15] : fr[7];
            float pm = f0*ma.x + f1*ma.y + f2*ma.z + f3*ma.w
                     + f4*mb4.x + f5*mb4.y + f6*mb4.z + f7*mb4.w;
            pm += __shfl_xor_sync(0xffffffffu, pm, 1);
            if (half == 0) sMean[i] = pm;
        }
        __syncwarp();   // S7: sT1, sMean

        // ---- Phase 7: cov[i][jb+r] = Q + T1[jb+r][:] . F[i][:]  (symmetry) ----
        {
            float a0 = pQ[0], a1 = pQ[1], a2 = pQ[2], a3 = pQ[3];
            float a4 = pQ[4], a5 = pQ[5], a6 = pQ[6], a7 = pQ[7];
            #pragma unroll
            for (int kc = 0; kc < 4; ++kc) {
                const float f0 = fr[kc*4], f1 = fr[kc*4+1], f2 = fr[kc*4+2], f3 = fr[kc*4+3];
                const float4 t0 = *(const float4*)(sT1 + (jb + 0) * SW + kc * 4);
                const float4 t1 = *(const float4*)(sT1 + (jb + 1) * SW + kc * 4);
                const float4 t2 = *(const float4*)(sT1 + (jb + 2) * SW + kc * 4);
                const float4 t3 = *(const float4*)(sT1 + (jb + 3) * SW + kc * 4);
                const float4 t4 = *(const float4*)(sT1 + (jb + 4) * SW + kc * 4);
                const float4 t5 = *(const float4*)(sT1 + (jb + 5) * SW + kc * 4);
                const float4 t6 = *(const float4*)(sT1 + (jb + 6) * SW + kc * 4);
                const float4 t7 = *(const float4*)(sT1 + (jb + 7) * SW + kc * 4);
                a0 += f0*t0.x + f1*t0.y + f2*t0.z + f3*t0.w;
                a1 += f0*t1.x + f1*t1.y + f2*t1.z + f3*t1.w;
                a2 += f0*t2.x + f1*t2.y + f2*t2.z + f3*t2.w;
                a3 += f0*t3.x + f1*t3.y + f2*t3.z + f3*t3.w;
                a4 += f0*t4.x + f1*t4.y + f2*t4.z + f3*t4.w;
                a5 += f0*t5.x + f1*t5.y + f2*t5.z + f3*t5.w;
                a6 += f0*t6.x + f1*t6.y + f2*t6.z + f3*t6.w;
                a7 += f0*t7.x + f1*t7.y + f2*t7.z + f3*t7.w;
            }
            cCov[0]=a0; cCov[1]=a1; cCov[2]=a2; cCov[3]=a3;
            cCov[4]=a4; cCov[5]=a5; cCov[6]=a6; cCov[7]=a7;
        }

        // ---- prefetch Q for t+1 (consumed only at next phase 7: full-iter hiding) ----
        if (t + 1 < Tn) {
            const float4 c = *(const float4*)(QG + (size_t)(t + 1) * 256 + lane * 8);
            const float4 d = *(const float4*)(QG + (size_t)(t + 1) * 256 + lane * 8 + 4);
            pQ[0]=c.x; pQ[1]=c.y; pQ[2]=c.z; pQ[3]=c.w; pQ[4]=d.x; pQ[5]=d.y; pQ[6]=d.z; pQ[7]=d.w;
        }
        // no sync needed here: next-iter smem writes (sH) were last read before S3;
        // sMean write (phase 6) is separated from next-iter read by S7.
    }
}

extern "C" void kernel_launch(void* const* d_in, const int* in_sizes, int n_in,
                              void* d_out, int out_size) {
    const float* y  = (const float*)d_in[0];
    const float* F  = (const float*)d_in[1];
    const float* H  = (const float*)d_in[2];
    const float* Q  = (const float*)d_in[3];
    const float* R  = (const float*)d_in[4];
    const float* im = (const float*)d_in[5];
    const float* ic = (const float*)d_in[6];

    float* out       = (float*)d_out;
    float* out_means = out;                                    // G*T*S
    float* out_covs  = out_means + (size_t)Gn * Tn * Sn;       // G*T*S*S
    float* out_R     = out_covs  + (size_t)Gn * Tn * Sn * Sn;  // G*T*M*M
    float* out_H     = out_R     + (size_t)Gn * Tn * Mn * Mn;  // G*T*M*S

    kalman_kernel<<<Gn, 32>>>(y, F, H, Q, R, im, ic,
                              out_means, out_covs, out_R, out_H);
}